// round 14
// baseline (speedup 1.0000x reference)
#include <cuda_runtime.h>
#include <cuda_bf16.h>
#include <cstdint>
#include <math.h>

#define HWSZ 262144   // 512*512
#define WDIM 512
#define CDIM 64

__device__ __nv_bfloat16 g_h1[2ull * HWSZ * 64];   // per-pixel H1 table, 64 MB
__device__ __nv_bfloat16 g_WcT[64 * 192];   // combined layer1 weight, [out j][k]
__device__ float g_bc[64];
__device__ __nv_bfloat16 g_w2T[32 * 64];    // [j][k] bf16
__device__ __nv_bfloat16 g_w3T[16 * 32];    // [j][k] bf16
__device__ int   g_coord64;
__device__ unsigned g_bitmap[2 * 8192];     // referenced-pixel bitmap (64 KB)

__device__ __forceinline__ float gelu_exact(float x) {
    return 0.5f * x * (1.0f + erff(x * 0.70710678118654752f));
}

// ---- warp-MMA helpers ----
__device__ __forceinline__ uint32_t smem_u32(const void* p) {
    uint32_t a;
    asm("{ .reg .u64 t; cvta.to.shared.u64 t, %1; cvt.u32.u64 %0, t; }" : "=r"(a) : "l"(p));
    return a;
}
__device__ __forceinline__ void ldsm4(uint32_t* r, uint32_t addr) {
    asm volatile("ldmatrix.sync.aligned.m8n8.x4.shared.b16 {%0,%1,%2,%3}, [%4];"
        : "=r"(r[0]), "=r"(r[1]), "=r"(r[2]), "=r"(r[3]) : "r"(addr));
}
__device__ __forceinline__ void ldsm2(uint32_t* r, uint32_t addr) {
    asm volatile("ldmatrix.sync.aligned.m8n8.x2.shared.b16 {%0,%1}, [%2];"
        : "=r"(r[0]), "=r"(r[1]) : "r"(addr));
}
__device__ __forceinline__ void mma16816(float* d, const uint32_t* a, const uint32_t* b) {
    asm volatile("mma.sync.aligned.m16n8k16.row.col.f32.bf16.bf16.f32 "
        "{%0,%1,%2,%3}, {%4,%5,%6,%7}, {%8,%9}, {%0,%1,%2,%3};"
        : "+f"(d[0]), "+f"(d[1]), "+f"(d[2]), "+f"(d[3])
        : "r"(a[0]), "r"(a[1]), "r"(a[2]), "r"(a[3]), "r"(b[0]), "r"(b[1]));
}
__device__ __forceinline__ unsigned bf2pack(float a, float b) {
    __nv_bfloat162 h = __float22bfloat162_rn(make_float2(a, b));
    return *reinterpret_cast<unsigned*>(&h);
}

#define XPITCH  384
#define H1PITCH 144
#define H2PITCH 80
#define H3PITCH 48

// ---------- l1_kernel SMEM layout ----------
#define L1_T   0            // T fp32 [64][68] = 17408
#define L1_H1  0            // overlays T after staging (64*144 = 9216)
#define L1_X   17408        // 64*384 = 24576 -> 41984 (swizzled)
#define L1_W   41984        // 64*384 = 24576 -> 66560 (swizzled)
#define L1_BC  66560        // 64 f32 -> 66816
#define SMEM_L1 66816

// ---------- point_kernel SMEM layout ----------
#define P_H1  0             // 128*144 = 18432
#define P_H2  18432         // 128*80 = 10240
#define P_H3  28672         // 128*48 = 6144 -> 34816
#define P_W2  34816         // 32*144 = 4608
#define P_W3  39424         // 16*80 = 1280 -> 40704
#define P_B2  40704         // 32 f32 -> 40832
#define P_B3  40832         // 16 f32 -> 40896
#define P_B4  40896         // 1 f32 -> 40912
#define P_W4  40912         // 16 f32 -> 40976
#define SMEM_P 40976

// ---------------------------------------------------------------------------
__global__ void setup_kernel(const float* __restrict__ w_lin,
                             const float* __restrict__ b_lin,
                             const float* __restrict__ w1,
                             const float* __restrict__ b1,
                             const float* __restrict__ w2,
                             const float* __restrict__ w3,
                             const void*  lidar_raw)
{
    int idx = blockIdx.x * blockDim.x + threadIdx.x;
    if (idx == 0) {
        const int* w = (const int*)lidar_raw;
        int all0 = 1;
        for (int i = 0; i < 32; i++) all0 &= (w[2 * i + 1] == 0);
        g_coord64 = all0;
    }
    if (idx < 12288) {               // WcT[j][k] bf16
        int j = idx / 192, k = idx % 192;
        float s;
        if (k < 128) {
            float s0 = 0.f, s1 = 0.f, s2 = 0.f, s3 = 0.f;
#pragma unroll 4
            for (int m = 0; m < 64; m += 4) {
                s0 = fmaf(w_lin[k * 64 + m],     w1[(m)     * 64 + j], s0);
                s1 = fmaf(w_lin[k * 64 + m + 1], w1[(m + 1) * 64 + j], s1);
                s2 = fmaf(w_lin[k * 64 + m + 2], w1[(m + 2) * 64 + j], s2);
                s3 = fmaf(w_lin[k * 64 + m + 3], w1[(m + 3) * 64 + j], s3);
            }
            s = (s0 + s1) + (s2 + s3);
        } else {
            s = w1[(64 + (k - 128)) * 64 + j];
        }
        g_WcT[idx] = __float2bfloat16(s);
    } else if (idx < 12352) {        // bc
        int j = idx - 12288;
        float s = b1[j];
        for (int m = 0; m < 64; m++) s = fmaf(b_lin[m], w1[m * 64 + j], s);
        g_bc[j] = s;
    } else if (idx < 14400) {        // w2T bf16
        int t = idx - 12352; int j = t / 64, k = t % 64;
        g_w2T[t] = __float2bfloat16(w2[k * 32 + j]);
    } else if (idx < 14912) {        // w3T bf16
        int t = idx - 14400; int j = t / 32, k = t % 32;
        g_w3T[t] = __float2bfloat16(w3[k * 16 + j]);
    }
}

// ---------------------------------------------------------------------------
// Bitmap: mark referenced pixels. Idempotent across graph replays.
// ---------------------------------------------------------------------------
__global__ void bitmap_kernel(const void* __restrict__ lc_raw,
                              const void* __restrict__ rc_raw,
                              int Nl, int Nr)
{
    int pt = blockIdx.x * 256 + threadIdx.x;
    int b = blockIdx.y;
    int N = Nl + Nr;
    if (pt >= N) return;
    int is64 = g_coord64;
    long long r, c;
    if (pt < Nl) {
        long long base = ((long long)b * Nl + pt) * 3;
        if (is64) { const long long* lc = (const long long*)lc_raw; r = lc[base + 1]; c = lc[base + 2]; }
        else      { const int*       lc = (const int*)lc_raw;       r = lc[base + 1]; c = lc[base + 2]; }
    } else {
        long long base = ((long long)b * Nr + (pt - Nl)) * 3;
        if (is64) { const long long* rc = (const long long*)rc_raw; r = rc[base + 1]; c = rc[base + 2]; }
        else      { const int*       rc = (const int*)rc_raw;       r = rc[base + 1]; c = rc[base + 2]; }
    }
    unsigned pix = (unsigned)(r * WDIM + c);
    atomicOr(&g_bitmap[b * 8192 + (pix >> 5)], 1u << (pix & 31));
}

// ---------------------------------------------------------------------------
// l1_kernel: stream maps (64-px tile), transpose-stage X (gated), HMMA layer1,
// gated gelu, gated copy of H1 rows to gmem table.
// ---------------------------------------------------------------------------
__global__ __launch_bounds__(256, 3)
void l1_kernel(const float* __restrict__ p0, const float* __restrict__ p1,
               const float* __restrict__ fl)
{
    extern __shared__ char sm[];
    uint32_t sbase = smem_u32(sm);
    float (*T)[68] = (float(*)[68])(sm + L1_T);

    int tid = threadIdx.x;
    int w = tid >> 5, lane = tid & 31;
    int b = blockIdx.y;
    size_t hw0 = (size_t)blockIdx.x * 64;
    uint2 mv = *(const uint2*)&g_bitmap[b * 8192 + (hw0 >> 5)];
    if ((mv.x | mv.y) == 0) return;

    // stage Wc (swizzled, pitch 384) + bc
    for (int i = tid; i < 1536; i += 256) {
        int j = i / 24, gg = i % 24;
        *(uint4*)(sm + L1_W + j * XPITCH + ((gg ^ (j & 7)) << 4)) =
            ((const uint4*)g_WcT)[j * 24 + gg];
    }
    if (tid < 64) ((float*)(sm + L1_BC))[tid] = g_bc[tid];

    // stream 3 maps: coalesced tile load -> gated swizzled X rows (bf16)
    const float* maps[3] = {p0, p1, fl};
#pragma unroll
    for (int m = 0; m < 3; m++) {
        const float* src = maps[m] + (size_t)b * CDIM * HWSZ;
#pragma unroll
        for (int it = 0; it < 4; it++) {
            int i = it * 256 + tid;
            int c = i >> 4, x4 = (i & 15) * 4;
            float4 v = *(const float4*)(src + (size_t)c * HWSZ + hw0 + x4);
            *(float4*)&T[c][x4 ^ ((c >> 3) << 2)] = v;
        }
        __syncthreads();
#pragma unroll
        for (int it = 0; it < 2; it++) {
            int i = it * 256 + tid;
            int y = i >> 3, gg = i & 7;
            unsigned bit = (y < 32) ? (mv.x >> y) : (mv.y >> (y - 32));
            if (bit & 1) {
                int yl = y & 3, y4 = y & ~3;
                int ch0 = gg * 8;
                float f[8];
#pragma unroll
                for (int k = 0; k < 8; k++) {
                    int ch = ch0 + k;
                    f[k] = T[ch][(y4 ^ ((ch >> 3) << 2)) + yl];
                }
                uint4 o;
                o.x = bf2pack(f[0], f[1]);
                o.y = bf2pack(f[2], f[3]);
                o.z = bf2pack(f[4], f[5]);
                o.w = bf2pack(f[6], f[7]);
                int G = m * 8 + gg;
                *(uint4*)(sm + L1_X + y * XPITCH + ((G ^ (y & 7)) << 4)) = o;
            }
        }
        __syncthreads();
    }

    // layer 1 MMA: warp w -> pg=w&1 (32 px), oh=w>>1 (16 outs)
    int pg = w & 1, oh = w >> 1;
    int g = lane >> 2, t = lane & 3;
    int r7 = lane & 7;
    uint32_t a_row = r7 + ((lane >> 3) & 1) * 8;
    uint32_t a_kt  = (lane >> 4) & 1;
    uint32_t b_kt  = (lane >> 3) & 1;
    uint32_t b_prow = ((lane >> 4) & 1) * 8 + r7;

    float D[2][2][4] = {};
    {
        uint32_t aB0 = sbase + L1_X + (pg * 32 + a_row) * XPITCH;
        uint32_t aB1 = aB0 + 16 * XPITCH;
        uint32_t bB0 = sbase + L1_W + (oh * 16 + b_prow) * XPITCH;
#pragma unroll
        for (int kk = 0; kk < 12; kk++) {
            uint32_t ga = (uint32_t)((2 * kk + a_kt) ^ r7) << 4;
            uint32_t gb = (uint32_t)((2 * kk + b_kt) ^ r7) << 4;
            uint32_t a0[4], a1[4], bf[4];
            ldsm4(a0, aB0 + ga);
            ldsm4(a1, aB1 + ga);
            ldsm4(bf, bB0 + gb);      // n-tiles j=0,1
            mma16816(D[0][0], a0, bf + 0);
            mma16816(D[1][0], a1, bf + 0);
            mma16816(D[0][1], a0, bf + 2);
            mma16816(D[1][1], a1, bf + 2);
        }
    }

    // gated bias + gelu -> H1 smem (overlays long-dead T region)
    {
        const float* bcs = (const float*)(sm + L1_BC);
#pragma unroll
        for (int mi = 0; mi < 2; mi++) {
            int p0r = pg * 32 + mi * 16 + g;
            int p1r = p0r + 8;
            unsigned bit0 = ((p0r < 32) ? (mv.x >> p0r) : (mv.y >> (p0r - 32))) & 1;
            unsigned bit1 = ((p1r < 32) ? (mv.x >> p1r) : (mv.y >> (p1r - 32))) & 1;
#pragma unroll
            for (int j = 0; j < 2; j++) {
                int c0 = oh * 16 + j * 8 + 2 * t;
                float b0v = bcs[c0], b1v = bcs[c0 + 1];
                if (bit0)
                    *(unsigned*)(sm + L1_H1 + p0r * H1PITCH + c0 * 2) =
                        bf2pack(gelu_exact(D[mi][j][0] + b0v), gelu_exact(D[mi][j][1] + b1v));
                if (bit1)
                    *(unsigned*)(sm + L1_H1 + p1r * H1PITCH + c0 * 2) =
                        bf2pack(gelu_exact(D[mi][j][2] + b0v), gelu_exact(D[mi][j][3] + b1v));
            }
        }
    }
    __syncthreads();

    // gated copy-out: H1 rows (128B) -> g_h1 table
    {
        __nv_bfloat16* dst = g_h1 + ((size_t)b * HWSZ + hw0) * 64;
#pragma unroll
        for (int it = 0; it < 2; it++) {
            int i = it * 256 + tid;
            int y = i >> 3, gg = i & 7;
            unsigned bit = (y < 32) ? (mv.x >> y) : (mv.y >> (y - 32));
            if (bit & 1)
                *(uint4*)((char*)dst + y * 128 + gg * 16) =
                    *(const uint4*)(sm + L1_H1 + y * H1PITCH + gg * 16);
        }
    }
}

// ---------------------------------------------------------------------------
// point_kernel: gather H1 rows + HMMA layers 2-4. 128 points/block, 256 thr.
// ---------------------------------------------------------------------------
__global__ __launch_bounds__(256, 4)
void point_kernel(const void* __restrict__ lc_raw, const void* __restrict__ rc_raw,
                  const float* __restrict__ w4, const float* __restrict__ b2,
                  const float* __restrict__ b3, const float* __restrict__ b4,
                  float* __restrict__ out, int Nl, int Nr)
{
    extern __shared__ char sm[];
    uint32_t sbase = smem_u32(sm);

    int tid = threadIdx.x;
    int w = tid >> 5, lane = tid & 31;
    int b = blockIdx.y;
    int N = Nl + Nr;
    int pt0 = blockIdx.x * 128;

    // stage weights
    if (tid < 256) {                             // W2: 32 rows x 8 granules
        int j = tid >> 3, gq = tid & 7;
        *(uint4*)(sm + P_W2 + j * H1PITCH + gq * 16) = ((const uint4*)g_w2T)[j * 8 + gq];
    }
    if (tid < 64) {                              // W3: 16 rows x 4 granules
        int j = tid >> 2, gq = tid & 3;
        *(uint4*)(sm + P_W3 + j * H2PITCH + gq * 16) = ((const uint4*)g_w3T)[j * 4 + gq];
    }
    if (tid < 32) ((float*)(sm + P_B2))[tid] = b2[tid];
    if (tid < 16) ((float*)(sm + P_B3))[tid] = b3[tid];
    if (tid < 16) ((float*)(sm + P_W4))[tid] = w4[tid];
    if (tid == 0) ((float*)(sm + P_B4))[0] = b4[0];

    // gather: 2 threads per point, 4x16B each (128B H1 row)
    {
        int is64 = g_coord64;
        int p = tid >> 1, half = tid & 1;
        int pt = pt0 + p;
        const __nv_bfloat16* rowptr = nullptr;
        if (pt < N) {
            long long r, c;
            if (pt < Nl) {
                long long base = ((long long)b * Nl + pt) * 3;
                if (is64) { const long long* lc = (const long long*)lc_raw; r = lc[base + 1]; c = lc[base + 2]; }
                else      { const int*       lc = (const int*)lc_raw;       r = lc[base + 1]; c = lc[base + 2]; }
            } else {
                long long base = ((long long)b * Nr + (pt - Nl)) * 3;
                if (is64) { const long long* rc = (const long long*)rc_raw; r = rc[base + 1]; c = rc[base + 2]; }
                else      { const int*       rc = (const int*)rc_raw;       r = rc[base + 1]; c = rc[base + 2]; }
            }
            rowptr = g_h1 + 64ull * ((size_t)b * HWSZ + (size_t)r * WDIM + (size_t)c);
        }
#pragma unroll
        for (int gi = 0; gi < 4; gi++) {
            int g = half * 4 + gi;
            uint4 v = make_uint4(0, 0, 0, 0);
            if (rowptr) v = *(const uint4*)((const char*)rowptr + g * 16);
            *(uint4*)(sm + P_H1 + p * H1PITCH + g * 16) = v;
        }
    }
    __syncthreads();

    int pg = w & 3, oh = w >> 2;
    int g = lane >> 2, t = lane & 3;
    int r7 = lane & 7;
    uint32_t a_row = r7 + ((lane >> 3) & 1) * 8;
    uint32_t a_kt  = (lane >> 4) & 1;
    uint32_t b_kt  = (lane >> 3) & 1;
    uint32_t b_prow = ((lane >> 4) & 1) * 8 + r7;

    // layer 2: H1[128x64] @ W2T[32x64]^T, warp -> (32 pts, 16 outs)
    {
        float D[2][2][4] = {};
        uint32_t aB0 = sbase + P_H1 + (pg * 32 + a_row) * H1PITCH + a_kt * 16;
        uint32_t aB1 = aB0 + 16 * H1PITCH;
        uint32_t bB  = sbase + P_W2 + (oh * 16 + b_prow) * H1PITCH + b_kt * 16;
#pragma unroll
        for (int kk = 0; kk < 4; kk++) {
            uint32_t a0[4], a1[4], bf[4];
            ldsm4(a0, aB0 + kk * 32);
            ldsm4(a1, aB1 + kk * 32);
            ldsm4(bf, bB + kk * 32);
            mma16816(D[0][0], a0, bf + 0);
            mma16816(D[1][0], a1, bf + 0);
            mma16816(D[0][1], a0, bf + 2);
            mma16816(D[1][1], a1, bf + 2);
        }
        const float* b2s = (const float*)(sm + P_B2);
#pragma unroll
        for (int mi = 0; mi < 2; mi++) {
            int p0r = pg * 32 + mi * 16 + g;
#pragma unroll
            for (int j = 0; j < 2; j++) {
                int c0 = oh * 16 + j * 8 + 2 * t;
                float b0v = b2s[c0], b1v = b2s[c0 + 1];
                *(unsigned*)(sm + P_H2 + p0r * H2PITCH + c0 * 2) =
                    bf2pack(gelu_exact(D[mi][j][0] + b0v), gelu_exact(D[mi][j][1] + b1v));
                *(unsigned*)(sm + P_H2 + (p0r + 8) * H2PITCH + c0 * 2) =
                    bf2pack(gelu_exact(D[mi][j][2] + b0v), gelu_exact(D[mi][j][3] + b1v));
            }
        }
    }
    __syncthreads();

    // layer 3: H2[128x32] @ W3T[16x32]^T, warp -> (32 pts, 8 outs)
    {
        int o3 = w >> 2;
        float D[2][4] = {};
        uint32_t aB0 = sbase + P_H2 + (pg * 32 + a_row) * H2PITCH + a_kt * 16;
        uint32_t aB1 = aB0 + 16 * H2PITCH;
        uint32_t bB  = sbase + P_W3 + (o3 * 8 + r7) * H2PITCH + b_kt * 16;
#pragma unroll
        for (int kk = 0; kk < 2; kk++) {
            uint32_t a0[4], a1[4], bf[2];
            ldsm4(a0, aB0 + kk * 32);
            ldsm4(a1, aB1 + kk * 32);
            ldsm2(bf, bB + kk * 32);
            mma16816(D[0], a0, bf);
            mma16816(D[1], a1, bf);
        }
        const float* b3s = (const float*)(sm + P_B3);
#pragma unroll
        for (int mi = 0; mi < 2; mi++) {
            int p0r = pg * 32 + mi * 16 + g;
            int c0 = o3 * 8 + 2 * t;
            float b0v = b3s[c0], b1v = b3s[c0 + 1];
            *(unsigned*)(sm + P_H3 + p0r * H3PITCH + c0 * 2) =
                bf2pack(gelu_exact(D[mi][0] + b0v), gelu_exact(D[mi][1] + b1v));
            *(unsigned*)(sm + P_H3 + (p0r + 8) * H3PITCH + c0 * 2) =
                bf2pack(gelu_exact(D[mi][2] + b0v), gelu_exact(D[mi][3] + b1v));
        }
    }
    __syncthreads();

    // layer 4: 16 -> 1, sigmoid. threads 0-127, one point each
    if (tid < 128) {
        uint4 v0 = *(const uint4*)(sm + P_H3 + tid * H3PITCH);
        uint4 v1 = *(const uint4*)(sm + P_H3 + tid * H3PITCH + 16);
        const float* w4s = (const float*)(sm + P_W4);
        unsigned uu[8] = {v0.x, v0.y, v0.z, v0.w, v1.x, v1.y, v1.z, v1.w};
        float s = ((const float*)(sm + P_B4))[0];
#pragma unroll
        for (int q = 0; q < 8; q++) {
            float2 f = __bfloat1622float2(*reinterpret_cast<__nv_bfloat162*>(&uu[q]));
            s = fmaf(f.x, w4s[2 * q], s);
            s = fmaf(f.y, w4s[2 * q + 1], s);
        }
        int pt = pt0 + tid;
        if (pt < N) out[(size_t)b * N + pt] = 1.f / (1.f + expf(-s));
    }
}

// ---------------------------------------------------------------------------
extern "C" void kernel_launch(void* const* d_in, const int* in_sizes, int n_in,
                              void* d_out, int out_size)
{
    const float* p0    = (const float*)d_in[0];
    const float* p1    = (const float*)d_in[1];
    const float* fl    = (const float*)d_in[2];
    const void*  lc    = d_in[3];
    const void*  rc    = d_in[4];
    const float* w_lin = (const float*)d_in[5];
    const float* b_lin = (const float*)d_in[6];
    const float* w1    = (const float*)d_in[7];
    const float* b1    = (const float*)d_in[8];
    const float* w2    = (const float*)d_in[9];
    const float* b2    = (const float*)d_in[10];
    const float* w3    = (const float*)d_in[11];
    const float* b3    = (const float*)d_in[12];
    const float* w4    = (const float*)d_in[13];
    const float* b4    = (const float*)d_in[14];

    int B  = in_sizes[0] / (CDIM * HWSZ);   // = 2
    int Nl = in_sizes[3] / (B * 3);
    int Nr = in_sizes[4] / (B * 3);
    int N  = Nl + Nr;

    setup_kernel<<<59, 256>>>(w_lin, b_lin, w1, b1, w2, w3, lc);

    dim3 bg((N + 255) / 256, B);
    bitmap_kernel<<<bg, 256>>>(lc, rc, Nl, Nr);

    cudaFuncSetAttribute(l1_kernel, cudaFuncAttributeMaxDynamicSharedMemorySize, SMEM_L1);
    dim3 lg(HWSZ / 64, B);
    l1_kernel<<<lg, 256, SMEM_L1>>>(p0, p1, fl);

    cudaFuncSetAttribute(point_kernel, cudaFuncAttributeMaxDynamicSharedMemorySize, SMEM_P);
    dim3 mg((N + 127) / 128, B);
    point_kernel<<<mg, 256, SMEM_P>>>(lc, rc, w4, b2, b3, b4, (float*)d_out, Nl, Nr);
}

// round 15
// speedup vs baseline: 1.1814x; 1.1814x over previous
#include <cuda_runtime.h>
#include <cuda_bf16.h>
#include <cstdint>
#include <math.h>

#define HWSZ 262144   // 512*512
#define WDIM 512
#define CDIM 64

// Scratch: interleaved (b, hw, 192ch) bf16 layout. ~192 MB.
__device__ __nv_bfloat16 g_scratch[2ull * HWSZ * 192];
__device__ __nv_bfloat16 g_WcT[64 * 192];   // combined layer1 weight, [out j][k]
__device__ float g_bc[64];
__device__ __nv_bfloat16 g_w2T[32 * 64];    // [j][k] bf16
__device__ __nv_bfloat16 g_w3T[16 * 32];    // [j][k] bf16
__device__ int   g_coord64;
__device__ unsigned g_bitmap[2 * 8192];     // referenced-pixel bitmap (64 KB)

__device__ __forceinline__ float gelu_exact(float x) {
    return 0.5f * x * (1.0f + erff(x * 0.70710678118654752f));
}

// ---- warp-MMA helpers ----
__device__ __forceinline__ uint32_t smem_u32(const void* p) {
    uint32_t a;
    asm("{ .reg .u64 t; cvta.to.shared.u64 t, %1; cvt.u32.u64 %0, t; }" : "=r"(a) : "l"(p));
    return a;
}
__device__ __forceinline__ void ldsm4(uint32_t* r, uint32_t addr) {
    asm volatile("ldmatrix.sync.aligned.m8n8.x4.shared.b16 {%0,%1,%2,%3}, [%4];"
        : "=r"(r[0]), "=r"(r[1]), "=r"(r[2]), "=r"(r[3]) : "r"(addr));
}
__device__ __forceinline__ void ldsm2(uint32_t* r, uint32_t addr) {
    asm volatile("ldmatrix.sync.aligned.m8n8.x2.shared.b16 {%0,%1}, [%2];"
        : "=r"(r[0]), "=r"(r[1]) : "r"(addr));
}
__device__ __forceinline__ void mma16816(float* d, const uint32_t* a, const uint32_t* b) {
    asm volatile("mma.sync.aligned.m16n8k16.row.col.f32.bf16.bf16.f32 "
        "{%0,%1,%2,%3}, {%4,%5,%6,%7}, {%8,%9}, {%0,%1,%2,%3};"
        : "+f"(d[0]), "+f"(d[1]), "+f"(d[2]), "+f"(d[3])
        : "r"(a[0]), "r"(a[1]), "r"(a[2]), "r"(a[3]), "r"(b[0]), "r"(b[1]));
}
__device__ __forceinline__ unsigned bf2pack(float a, float b) {
    __nv_bfloat162 h = __float22bfloat162_rn(make_float2(a, b));
    return *reinterpret_cast<unsigned*>(&h);
}

// SMEM layout (bytes). X/B use pitch 384 with per-row XOR granule swizzle.
#define XPITCH  384
#define H1PITCH 144
#define H2PITCH 80
#define H3PITCH 48
#define SM_X   0                    // 128*384 = 49152 (swizzled)
#define SM_H1  0                    // overlays X after layer1 (128*144=18432)
#define SM_H2  18432                // 128*80 = 10240
#define SM_H3  28672                // 128*48 = 6144  -> 34816
#define SM_W2  34816                // 32*144 = 4608 (staged AFTER layer1)
#define SM_W3  39424                // 16*80 = 1280  -> 40704 < 49152
#define SM_B   49152                // WcT 64*384 = 24576 (swizzled) -> 73728
#define SM_BC  73728                // 64 f32
#define SM_B2  73984                // 32 f32
#define SM_B3  74112                // 16 f32
#define SM_B4  74176                // 1 f32
#define SM_W4  74192                // 16 f32 -> 74256
#define SMEM_DYN 74256

// ---------------------------------------------------------------------------
__global__ void setup_kernel(const float* __restrict__ w_lin,
                             const float* __restrict__ b_lin,
                             const float* __restrict__ w1,
                             const float* __restrict__ b1,
                             const float* __restrict__ w2,
                             const float* __restrict__ w3,
                             const void*  lidar_raw)
{
    int idx = blockIdx.x * blockDim.x + threadIdx.x;
    if (idx == 0) {
        const int* w = (const int*)lidar_raw;
        int all0 = 1;
        for (int i = 0; i < 32; i++) all0 &= (w[2 * i + 1] == 0);
        g_coord64 = all0;
    }
    if (idx < 12288) {               // WcT[j][k] bf16
        int j = idx / 192, k = idx % 192;
        float s;
        if (k < 128) {
            float s0 = 0.f, s1 = 0.f, s2 = 0.f, s3 = 0.f;
#pragma unroll 4
            for (int m = 0; m < 64; m += 4) {
                s0 = fmaf(w_lin[k * 64 + m],     w1[(m)     * 64 + j], s0);
                s1 = fmaf(w_lin[k * 64 + m + 1], w1[(m + 1) * 64 + j], s1);
                s2 = fmaf(w_lin[k * 64 + m + 2], w1[(m + 2) * 64 + j], s2);
                s3 = fmaf(w_lin[k * 64 + m + 3], w1[(m + 3) * 64 + j], s3);
            }
            s = (s0 + s1) + (s2 + s3);
        } else {
            s = w1[(64 + (k - 128)) * 64 + j];
        }
        g_WcT[idx] = __float2bfloat16(s);
    } else if (idx < 12352) {        // bc
        int j = idx - 12288;
        float s = b1[j];
        for (int m = 0; m < 64; m++) s = fmaf(b_lin[m], w1[m * 64 + j], s);
        g_bc[j] = s;
    } else if (idx < 14400) {        // w2T bf16
        int t = idx - 12352; int j = t / 64, k = t % 64;
        g_w2T[t] = __float2bfloat16(w2[k * 32 + j]);
    } else if (idx < 14912) {        // w3T bf16
        int t = idx - 14400; int j = t / 32, k = t % 32;
        g_w3T[t] = __float2bfloat16(w3[k * 16 + j]);
    }
}

// ---------------------------------------------------------------------------
// Bitmap: mark referenced pixels. Idempotent across graph replays.
// ---------------------------------------------------------------------------
__global__ void bitmap_kernel(const void* __restrict__ lc_raw,
                              const void* __restrict__ rc_raw,
                              int Nl, int Nr)
{
    int pt = blockIdx.x * 256 + threadIdx.x;
    int b = blockIdx.y;
    int N = Nl + Nr;
    if (pt >= N) return;
    int is64 = g_coord64;
    long long r, c;
    if (pt < Nl) {
        long long base = ((long long)b * Nl + pt) * 3;
        if (is64) { const long long* lc = (const long long*)lc_raw; r = lc[base + 1]; c = lc[base + 2]; }
        else      { const int*       lc = (const int*)lc_raw;       r = lc[base + 1]; c = lc[base + 2]; }
    } else {
        long long base = ((long long)b * Nr + (pt - Nl)) * 3;
        if (is64) { const long long* rc = (const long long*)rc_raw; r = rc[base + 1]; c = rc[base + 2]; }
        else      { const int*       rc = (const int*)rc_raw;       r = rc[base + 1]; c = rc[base + 2]; }
    }
    unsigned pix = (unsigned)(r * WDIM + c);
    atomicOr(&g_bitmap[b * 8192 + (pix >> 5)], 1u << (pix & 31));
}

// ---------------------------------------------------------------------------
// Transpose (B,C,H,W) x3 fp32 maps -> bf16 scratch[b][hw][192ch]. Batch = arg.
// ---------------------------------------------------------------------------
__global__ __launch_bounds__(256)
void transpose_kernel(const float* __restrict__ p0,
                      const float* __restrict__ p1,
                      const float* __restrict__ fl, int b)
{
    __shared__ float T[64][68];
    int tid = threadIdx.x;
    size_t hw0 = (size_t)blockIdx.x * 64;
    uint2 mv = *(const uint2*)&g_bitmap[b * 8192 + (hw0 >> 5)];
    if ((mv.x | mv.y) == 0) return;
    const float* maps[3] = {p0, p1, fl};
#pragma unroll
    for (int m = 0; m < 3; m++) {
        const float* src = maps[m] + (size_t)b * CDIM * HWSZ;
#pragma unroll
        for (int it = 0; it < 4; it++) {
            int i = it * 256 + tid;
            int c = i >> 4, x4 = (i & 15) * 4;
            float4 v = *(const float4*)(src + (size_t)c * HWSZ + hw0 + x4);
            *(float4*)&T[c][x4 ^ ((c >> 3) << 2)] = v;
        }
        __syncthreads();
        __nv_bfloat16* dst = g_scratch + ((size_t)b * HWSZ + hw0) * 192 + m * 64;
#pragma unroll
        for (int it = 0; it < 2; it++) {
            int i = it * 256 + tid;
            int y = i >> 3, gg = i & 7;
            unsigned bit = (y < 32) ? (mv.x >> y) : (mv.y >> (y - 32));
            if (bit & 1) {
                int yl = y & 3, y4 = y & ~3;
                int ch0 = gg * 8;
                float f[8];
#pragma unroll
                for (int k = 0; k < 8; k++) {
                    int ch = ch0 + k;
                    f[k] = T[ch][(y4 ^ ((ch >> 3) << 2)) + yl];
                }
                uint4 o;
                o.x = bf2pack(f[0], f[1]);
                o.y = bf2pack(f[2], f[3]);
                o.z = bf2pack(f[4], f[5]);
                o.w = bf2pack(f[6], f[7]);
                *(uint4*)(dst + (size_t)y * 192 + ch0) = o;
            }
        }
        __syncthreads();
    }
}

// ---------------------------------------------------------------------------
// Fused gather + 3x HMMA layers + tiny layer4. 128 points/block. Batch = arg.
// ---------------------------------------------------------------------------
__global__ __launch_bounds__(256, 3)
void mlp_kernel(const void* __restrict__ lc_raw, const void* __restrict__ rc_raw,
                const float* __restrict__ w4, const float* __restrict__ b2,
                const float* __restrict__ b3, const float* __restrict__ b4,
                float* __restrict__ out, int Nl, int Nr, int b)
{
    extern __shared__ char sm[];
    uint32_t sbase = smem_u32(sm);

    int tid = threadIdx.x;
    int w = tid >> 5, lane = tid & 31;
    int N = Nl + Nr;
    int pt0 = blockIdx.x * 128;

    // ---- stage WcT (swizzled) + biases (W2/W3 staged after layer1) ----
    for (int i = tid; i < 1536; i += 256) {
        int j = i / 24, gg = i % 24;
        *(uint4*)(sm + SM_B + j * XPITCH + ((gg ^ (j & 7)) << 4)) =
            ((const uint4*)g_WcT)[j * 24 + gg];
    }
    if (tid < 64) ((float*)(sm + SM_BC))[tid] = g_bc[tid];
    if (tid < 32) ((float*)(sm + SM_B2))[tid] = b2[tid];
    if (tid < 16) ((float*)(sm + SM_B3))[tid] = b3[tid];
    if (tid < 16) ((float*)(sm + SM_W4))[tid] = w4[tid];
    if (tid == 0) ((float*)(sm + SM_B4))[0] = b4[0];

    // ---- gather: 2 threads per point, 12x16B each, swizzled X stores ----
    {
        int is64 = g_coord64;
        int p = tid >> 1, half = tid & 1;
        int p7 = p & 7;
        int pt = pt0 + p;
        const __nv_bfloat16* rowptr = nullptr;
        if (pt < N) {
            long long r, c;
            if (pt < Nl) {
                long long base = ((long long)b * Nl + pt) * 3;
                if (is64) { const long long* lc = (const long long*)lc_raw; r = lc[base + 1]; c = lc[base + 2]; }
                else      { const int*       lc = (const int*)lc_raw;       r = lc[base + 1]; c = lc[base + 2]; }
            } else {
                long long base = ((long long)b * Nr + (pt - Nl)) * 3;
                if (is64) { const long long* rc = (const long long*)rc_raw; r = rc[base + 1]; c = rc[base + 2]; }
                else      { const int*       rc = (const int*)rc_raw;       r = rc[base + 1]; c = rc[base + 2]; }
            }
            rowptr = g_scratch + 192ull * ((size_t)b * HWSZ + (size_t)r * WDIM + (size_t)c);
        }
#pragma unroll
        for (int gi = 0; gi < 12; gi++) {
            int g = half * 12 + gi;
            uint4 v = make_uint4(0, 0, 0, 0);
            if (rowptr) v = *(const uint4*)((const char*)rowptr + g * 16);
            *(uint4*)(sm + SM_X + p * XPITCH + ((g ^ p7) << 4)) = v;
        }
    }
    __syncthreads();

    int pg = w & 3, oh = w >> 2;      // point group (32 pts), output half
    int g = lane >> 2, t = lane & 3;
    int r7 = lane & 7;
    uint32_t a_row = r7 + ((lane >> 3) & 1) * 8;
    uint32_t a_kt  = (lane >> 4) & 1;
    uint32_t b_kt  = (lane >> 3) & 1;
    uint32_t b_prow = ((lane >> 4) & 1) * 8 + r7;   // row within 16-row j-pair

    // ---- layer 1: X[128x192] @ WcT[64x192]^T, warp -> (32 pts, 32 outs) ----
    {
        float D[2][4][4] = {};
        uint32_t aB0 = sbase + SM_X + (pg * 32 + a_row) * XPITCH;
        uint32_t aB1 = aB0 + 16 * XPITCH;
        uint32_t bB0 = sbase + SM_B + (oh * 32 + b_prow) * XPITCH;
        uint32_t bB1 = bB0 + 16 * XPITCH;
#pragma unroll
        for (int kk = 0; kk < 12; kk++) {
            uint32_t ga = (uint32_t)((2 * kk + a_kt) ^ r7) << 4;
            uint32_t gb = (uint32_t)((2 * kk + b_kt) ^ r7) << 4;
            uint32_t a0[4], a1[4], bf0[4], bf1[4];
            ldsm4(a0, aB0 + ga);
            ldsm4(a1, aB1 + ga);
            ldsm4(bf0, bB0 + gb);     // n-tiles j=0,1
            mma16816(D[0][0], a0, bf0 + 0);
            mma16816(D[1][0], a1, bf0 + 0);
            mma16816(D[0][1], a0, bf0 + 2);
            mma16816(D[1][1], a1, bf0 + 2);
            ldsm4(bf1, bB1 + gb);     // n-tiles j=2,3
            mma16816(D[0][2], a0, bf1 + 0);
            mma16816(D[1][2], a1, bf1 + 0);
            mma16816(D[0][3], a0, bf1 + 2);
            mma16816(D[1][3], a1, bf1 + 2);
        }
        __syncthreads();   // X reads done before H1/W2/W3 overlay it

        const float* bcs = (const float*)(sm + SM_BC);
#pragma unroll
        for (int mi = 0; mi < 2; mi++) {
            int p0r = pg * 32 + mi * 16 + g;
#pragma unroll
            for (int j = 0; j < 4; j++) {
                int c0 = (oh * 4 + j) * 8 + 2 * t;
                float b0v = bcs[c0], b1v = bcs[c0 + 1];
                *(unsigned*)(sm + SM_H1 + p0r * H1PITCH + c0 * 2) =
                    bf2pack(gelu_exact(D[mi][j][0] + b0v), gelu_exact(D[mi][j][1] + b1v));
                *(unsigned*)(sm + SM_H1 + (p0r + 8) * H1PITCH + c0 * 2) =
                    bf2pack(gelu_exact(D[mi][j][2] + b0v), gelu_exact(D[mi][j][3] + b1v));
            }
        }
        if (tid < 256) {                             // W2: 32 rows x 8 granules
            int j = tid >> 3, gq = tid & 7;
            *(uint4*)(sm + SM_W2 + j * H1PITCH + gq * 16) = ((const uint4*)g_w2T)[j * 8 + gq];
        }
        if (tid < 64) {                              // W3: 16 rows x 4 granules
            int j = tid >> 2, gq = tid & 3;
            *(uint4*)(sm + SM_W3 + j * H2PITCH + gq * 16) = ((const uint4*)g_w3T)[j * 4 + gq];
        }
    }
    __syncthreads();

    // ---- layer 2: H1[128x64] @ W2T[32x64]^T, warp -> (32 pts, 16 outs) ----
    {
        float D[2][2][4] = {};
        uint32_t aB0 = sbase + SM_H1 + (pg * 32 + a_row) * H1PITCH + a_kt * 16;
        uint32_t aB1 = aB0 + 16 * H1PITCH;
        uint32_t bB  = sbase + SM_W2 + (oh * 16 + b_prow) * H1PITCH + b_kt * 16;
#pragma unroll
        for (int kk = 0; kk < 4; kk++) {
            uint32_t a0[4], a1[4], bf[4];
            ldsm4(a0, aB0 + kk * 32);
            ldsm4(a1, aB1 + kk * 32);
            ldsm4(bf, bB + kk * 32);
            mma16816(D[0][0], a0, bf + 0);
            mma16816(D[1][0], a1, bf + 0);
            mma16816(D[0][1], a0, bf + 2);
            mma16816(D[1][1], a1, bf + 2);
        }
        const float* b2s = (const float*)(sm + SM_B2);
#pragma unroll
        for (int mi = 0; mi < 2; mi++) {
            int p0r = pg * 32 + mi * 16 + g;
#pragma unroll
            for (int j = 0; j < 2; j++) {
                int c0 = oh * 16 + j * 8 + 2 * t;
                float b0v = b2s[c0], b1v = b2s[c0 + 1];
                *(unsigned*)(sm + SM_H2 + p0r * H2PITCH + c0 * 2) =
                    bf2pack(gelu_exact(D[mi][j][0] + b0v), gelu_exact(D[mi][j][1] + b1v));
                *(unsigned*)(sm + SM_H2 + (p0r + 8) * H2PITCH + c0 * 2) =
                    bf2pack(gelu_exact(D[mi][j][2] + b0v), gelu_exact(D[mi][j][3] + b1v));
            }
        }
    }
    __syncthreads();

    // ---- layer 3: H2[128x32] @ W3T[16x32]^T, warp -> (32 pts, 8 outs) ----
    {
        int o3 = w >> 2;
        float D[2][4] = {};
        uint32_t aB0 = sbase + SM_H2 + (pg * 32 + a_row) * H2PITCH + a_kt * 16;
        uint32_t aB1 = aB0 + 16 * H2PITCH;
        uint32_t bB  = sbase + SM_W3 + (o3 * 8 + r7) * H2PITCH + b_kt * 16;
#pragma unroll
        for (int kk = 0; kk < 2; kk++) {
            uint32_t a0[4], a1[4], bf[2];
            ldsm4(a0, aB0 + kk * 32);
            ldsm4(a1, aB1 + kk * 32);
            ldsm2(bf, bB + kk * 32);
            mma16816(D[0], a0, bf);
            mma16816(D[1], a1, bf);
        }
        const float* b3s = (const float*)(sm + SM_B3);
#pragma unroll
        for (int mi = 0; mi < 2; mi++) {
            int p0r = pg * 32 + mi * 16 + g;
            int c0 = o3 * 8 + 2 * t;
            float b0v = b3s[c0], b1v = b3s[c0 + 1];
            *(unsigned*)(sm + SM_H3 + p0r * H3PITCH + c0 * 2) =
                bf2pack(gelu_exact(D[mi][0] + b0v), gelu_exact(D[mi][1] + b1v));
            *(unsigned*)(sm + SM_H3 + (p0r + 8) * H3PITCH + c0 * 2) =
                bf2pack(gelu_exact(D[mi][2] + b0v), gelu_exact(D[mi][3] + b1v));
        }
    }
    __syncthreads();

    // ---- layer 4: 16 -> 1, sigmoid. threads 0-127, one point each ----
    if (tid < 128) {
        uint4 v0 = *(const uint4*)(sm + SM_H3 + tid * H3PITCH);
        uint4 v1 = *(const uint4*)(sm + SM_H3 + tid * H3PITCH + 16);
        const float* w4s = (const float*)(sm + SM_W4);
        unsigned uu[8] = {v0.x, v0.y, v0.z, v0.w, v1.x, v1.y, v1.z, v1.w};
        float s = ((const float*)(sm + SM_B4))[0];
#pragma unroll
        for (int q = 0; q < 8; q++) {
            float2 f = __bfloat1622float2(*reinterpret_cast<__nv_bfloat162*>(&uu[q]));
            s = fmaf(f.x, w4s[2 * q], s);
            s = fmaf(f.y, w4s[2 * q + 1], s);
        }
        int pt = pt0 + tid;
        if (pt < N) out[(size_t)b * N + pt] = 1.f / (1.f + expf(-s));
    }
}

// ---------------------------------------------------------------------------
extern "C" void kernel_launch(void* const* d_in, const int* in_sizes, int n_in,
                              void* d_out, int out_size)
{
    const float* p0    = (const float*)d_in[0];
    const float* p1    = (const float*)d_in[1];
    const float* fl    = (const float*)d_in[2];
    const void*  lc    = d_in[3];
    const void*  rc    = d_in[4];
    const float* w_lin = (const float*)d_in[5];
    const float* b_lin = (const float*)d_in[6];
    const float* w1    = (const float*)d_in[7];
    const float* b1    = (const float*)d_in[8];
    const float* w2    = (const float*)d_in[9];
    const float* b2    = (const float*)d_in[10];
    const float* w3    = (const float*)d_in[11];
    const float* b3    = (const float*)d_in[12];
    const float* w4    = (const float*)d_in[13];
    const float* b4    = (const float*)d_in[14];

    int B  = in_sizes[0] / (CDIM * HWSZ);   // = 2
    int Nl = in_sizes[3] / (B * 3);
    int Nr = in_sizes[4] / (B * 3);
    int N  = Nl + Nr;

    // One aux stream + fork/join events (host objects, created once; the GPU
    // work per call is identical every call).
    static cudaStream_t s_aux = nullptr;
    static cudaEvent_t s_fork = nullptr, s_join = nullptr;
    if (!s_aux) {
        cudaStreamCreateWithFlags(&s_aux, cudaStreamNonBlocking);
        cudaEventCreateWithFlags(&s_fork, cudaEventDisableTiming);
        cudaEventCreateWithFlags(&s_join, cudaEventDisableTiming);
    }

    setup_kernel<<<59, 256>>>(w_lin, b_lin, w1, b1, w2, w3, lc);

    dim3 bg((N + 255) / 256, B);
    bitmap_kernel<<<bg, 256>>>(lc, rc, Nl, Nr);

    cudaFuncSetAttribute(mlp_kernel, cudaFuncAttributeMaxDynamicSharedMemorySize, SMEM_DYN);

    // fork: batch 1 pipeline runs on s_aux concurrently with batch 0 on main
    cudaEventRecord(s_fork, 0);
    cudaStreamWaitEvent(s_aux, s_fork, 0);

    int tgrid = HWSZ / 64;
    int mgrid = (N + 127) / 128;

    // batch 0 on legacy stream
    transpose_kernel<<<tgrid, 256>>>(p0, p1, fl, 0);
    mlp_kernel<<<mgrid, 256, SMEM_DYN>>>(lc, rc, w4, b2, b3, b4, (float*)d_out, Nl, Nr, 0);

    // batch 1 on aux stream
    if (B > 1) {
        transpose_kernel<<<tgrid, 256, 0, s_aux>>>(p0, p1, fl, 1);
        mlp_kernel<<<mgrid, 256, SMEM_DYN, s_aux>>>(lc, rc, w4, b2, b3, b4, (float*)d_out, Nl, Nr, 1);
    }

    // join
    cudaEventRecord(s_join, s_aux);
    cudaStreamWaitEvent(0, s_join, 0);
}